// round 7
// baseline (speedup 1.0000x reference)
#include <cuda_runtime.h>
#include <cstdint>

#define Bsz 1024
#define Tt  128
#define Dd  64
#define Hh  256
#define MB  8
#define NT  512
#define GRID 128

typedef unsigned long long u64;

// ------------------- device scratch (precomputed, per call) -------------------
__device__ float tdhT_g[Dd * Hh];                    // td_h_W^T  [k][c]
__device__ float tdxT_g[Dd * Dd];                    // td_x_W^T  [k][j]
__device__ float Gh_g[Bsz * Tt * Hh];                // gamma_h   [b*T+t][256]
__device__ float alpha_g[Bsz * Tt * Dd];             // alpha     [b*T+t][64]
__device__ float zprep_g[(Bsz / 2) * Tt * 1024 * 2]; // lstm_b + m@Wm, paired

__device__ __forceinline__ u64 dup2(float w) {
    u64 r; asm("mov.b64 %0, {%1,%1};" : "=l"(r) : "f"(w)); return r;
}
__device__ __forceinline__ void upk2(u64 v, float& lo, float& hi) {
    asm("mov.b64 {%0,%1}, %2;" : "=f"(lo), "=f"(hi) : "l"(v));
}
__device__ __forceinline__ u64 fma2(u64 a, u64 b, u64 c) {
    u64 d; asm("fma.rn.f32x2 %0, %1, %2, %3;" : "=l"(d) : "l"(a), "l"(b), "l"(c)); return d;
}
__device__ __forceinline__ u64 add2(u64 a, u64 b) {
    u64 d; asm("add.rn.f32x2 %0, %1, %2;" : "=l"(d) : "l"(a), "l"(b)); return d;
}
__device__ __forceinline__ float sigf(float x) {
    return __fdividef(1.f, 1.f + __expf(-x));
}
__device__ __forceinline__ float tanhfast(float x) {
    return __fdividef(2.f, 1.f + __expf(-2.f * x)) - 1.f;
}

// ============================ precompute kernels ============================

__global__ void transpose_kernel(const float* __restrict__ tdhW,
                                 const float* __restrict__ tdxW) {
    int idx = blockIdx.x * 256 + threadIdx.x;
    if (idx < Hh * Dd) {                       // tdhW (256,64) -> [k][c]
        int c = idx >> 6, k = idx & 63;
        tdhT_g[k * Hh + c] = tdhW[idx];
    } else if (idx < Hh * Dd + Dd * Dd) {      // tdxW (64,64) -> [k][j]
        int e = idx - Hh * Dd;
        int j = e >> 6, k = e & 63;
        tdxT_g[k * Dd + j] = tdxW[e];
    }
}

// gamma_h AND (gamma_x -> alpha): 128 persistent blocks, weights staged once,
// t-loop inside (weight L2 traffic /128 vs per-(b,t)-block version).
__global__ void __launch_bounds__(256) pre_ga_kernel(
    const float* __restrict__ deltas, const float* __restrict__ masks,
    const float* __restrict__ tdhB, const float* __restrict__ tdxB,
    const float* __restrict__ wcW, const float* __restrict__ wcB)
{
    extern __shared__ float gsm[];
    float* tdh = gsm;                  // [64][256]
    float* tdx = tdh + 64 * 256;       // [64][64]
    float* wc  = tdx + 64 * 64;        // [128][64]
    float* dp  = wc + 128 * 64;        // [4][64][2]
    float* mp  = dp + 512;
    float* gxp = mp + 512;

    const int tid = threadIdx.x;
    const int bg  = blockIdx.x;        // batches [bg*8, bg*8+8)

    for (int e = tid; e < 64 * 256; e += 256) tdh[e] = tdhT_g[e];
    for (int e = tid; e < 64 * 64; e += 256)  tdx[e] = tdxT_g[e];
    for (int e = tid; e < 128 * 64; e += 256) wc[e]  = wcW[e];

    const float bh = tdhB[tid];
    const float bx = tdxB[tid & 63];
    const float bw = wcB[tid & 63];

    for (int tt = 0; tt < Tt; tt++) {
        __syncthreads();   // protect dp/mp reuse + (first iter) weight staging
        for (int e = tid; e < 8 * Dd; e += 256) {
            int r = e >> 6, k = e & 63;
            int off = ((bg * 8 + r) * Tt + tt) * Dd + k;
            dp[(r >> 1) * 128 + k * 2 + (r & 1)] = deltas[off];
            mp[(r >> 1) * 128 + k * 2 + (r & 1)] = masks[off];
        }
        __syncthreads();

        // ---- gamma_h: thread = column c ----
        {
            const int c = tid;
            u64 a[4];
            #pragma unroll
            for (int p = 0; p < 4; p++) a[p] = 0ULL;
            #pragma unroll 4
            for (int k = 0; k < Dd; k++) {
                u64 wd = dup2(tdh[k * Hh + c]);
                #pragma unroll
                for (int p = 0; p < 4; p++)
                    a[p] = fma2(*(const u64*)(dp + p * 128 + k * 2), wd, a[p]);
            }
            #pragma unroll
            for (int p = 0; p < 4; p++) {
                float a0, a1; upk2(a[p], a0, a1);
                Gh_g[((bg * 8 + 2 * p)     * Tt + tt) * Hh + c] = __expf(-fmaxf(a0 + bh, 0.f));
                Gh_g[((bg * 8 + 2 * p + 1) * Tt + tt) * Hh + c] = __expf(-fmaxf(a1 + bh, 0.f));
            }
        }

        // ---- gamma_x ----
        const int j = tid & 63, pg = tid >> 6;
        u64 g = dup2(bx);
        #pragma unroll 4
        for (int k = 0; k < Dd; k++)
            g = fma2(*(const u64*)(dp + pg * 128 + k * 2), dup2(tdx[k * Dd + j]), g);
        float g0, g1; upk2(g, g0, g1);
        gxp[pg * 128 + j * 2 + 0] = __expf(-fmaxf(g0, 0.f));
        gxp[pg * 128 + j * 2 + 1] = __expf(-fmaxf(g1, 0.f));
        __syncthreads();

        // ---- alpha ----
        u64 al = dup2(bw);
        #pragma unroll 4
        for (int k = 0; k < Dd; k++) {
            al = fma2(*(const u64*)(gxp + pg * 128 + k * 2), dup2(wc[k * Dd + j]), al);
            al = fma2(*(const u64*)(mp  + pg * 128 + k * 2), dup2(wc[(Dd + k) * Dd + j]), al);
        }
        float a0, a1; upk2(al, a0, a1);
        alpha_g[((bg * 8 + 2 * pg)     * Tt + tt) * Dd + j] = a0;
        alpha_g[((bg * 8 + 2 * pg + 1) * Tt + tt) * Dd + j] = a1;
    }
}

// zpre = lstm_b + m @ lstm_k[64:128], pair-interleaved (b even, b odd).
// grid (4 col-tiles, 512 b-pairs): W + bias staged ONCE, reused over all 128 t.
__global__ void __launch_bounds__(256) pre_z_kernel(
    const float* __restrict__ masks, const float* __restrict__ lstmK,
    const float* __restrict__ lstmB)
{
    extern __shared__ float psm[];
    float* W  = psm;               // [64][256]
    float* lb = W + 64 * 256;      // [256]
    float* mp = lb + 256;          // [16 t][64 k][2 par]
    const int tid = threadIdx.x;
    const int c0 = blockIdx.x * 256;
    const int bp = blockIdx.y;

    for (int e = tid; e < 64 * 256; e += 256) {
        int k = e >> 8, c = e & 255;
        W[e] = lstmK[(Dd + k) * 1024 + c0 + c];
    }
    lb[tid] = lstmB[c0 + tid];

    const int cq = tid & 63;
    const int pg = tid >> 6;

    for (int t0 = 0; t0 < Tt; t0 += 16) {
        __syncthreads();
        #pragma unroll
        for (int par = 0; par < 2; par++)
            for (int e = tid; e < 16 * 64; e += 256) {
                int tt = e >> 6, k = e & 63;
                mp[tt * 128 + k * 2 + par] =
                    masks[((2 * bp + par) * Tt + t0 + tt) * Dd + k];
            }
        __syncthreads();

        u64 acc[4][4];
        #pragma unroll
        for (int tt = 0; tt < 4; tt++)
            #pragma unroll
            for (int c = 0; c < 4; c++) acc[tt][c] = 0ULL;

        #pragma unroll 2
        for (int k = 0; k < Dd; k++) {
            float4 w = *(const float4*)(W + k * 256 + cq * 4);
            u64 w0 = dup2(w.x), w1 = dup2(w.y), w2 = dup2(w.z), w3 = dup2(w.w);
            #pragma unroll
            for (int tt = 0; tt < 4; tt++) {
                u64 m2 = *(const u64*)(mp + (pg * 4 + tt) * 128 + k * 2);
                acc[tt][0] = fma2(m2, w0, acc[tt][0]);
                acc[tt][1] = fma2(m2, w1, acc[tt][1]);
                acc[tt][2] = fma2(m2, w2, acc[tt][2]);
                acc[tt][3] = fma2(m2, w3, acc[tt][3]);
            }
        }
        float4 lbv = *(const float4*)(lb + cq * 4);
        u64 lb0 = dup2(lbv.x), lb1 = dup2(lbv.y), lb2 = dup2(lbv.z), lb3 = dup2(lbv.w);
        #pragma unroll
        for (int tt = 0; tt < 4; tt++) {
            int tg = t0 + pg * 4 + tt;
            int col = c0 + cq * 4;
            u64* dst = (u64*)(zprep_g + ((size_t)(bp * Tt + tg) * 1024 + col) * 2);
            dst[0] = add2(acc[tt][0], lb0);
            dst[1] = add2(acc[tt][1], lb1);
            dst[2] = add2(acc[tt][2], lb2);
            dst[3] = add2(acc[tt][3], lb3);
        }
    }
}

// ============================ main recurrent kernel ============================

struct __align__(16) Smem {
    float hist[Hh * Dd];      // 64 KB
    float frT[Dd * Dd];       // 16 KB
    float hq[Hh * 8];         //  8 KB  h: hq[k*8 + r]  (k-major, 8 rows contiguous)
    float cs[MB * Hh];        //  8 KB  c state [r][c]
    float zp[4 * 2 * 4 * Hh]; // 32 KB  gate acts [pair][col*2+par] (alias: x_h partials)
    float gh[MB * Hh];        //  8 KB  G_h[t+1] staging [r][c]
    float ccq[Dd * 8];        //  2 KB  c_c: ccq[j*8 + r]
    float xs[MB * Dd], ms[MB * Dd];
    float alp[4 * 2 * Dd];
    float xcp[4 * 2 * Dd], xhp[4 * 2 * Dd];
    float hist_b[Dd], fr_b[Dd];
};

__global__ void __launch_bounds__(NT, 1) rits_kernel(
    const float* __restrict__ values, const float* __restrict__ masks,
    const float* __restrict__ histW, const float* __restrict__ histB,
    const float* __restrict__ frW, const float* __restrict__ frB,
    const float* __restrict__ lstmK, const float* __restrict__ lstmRK,
    const float* __restrict__ outW, const float* __restrict__ outB,
    float* __restrict__ yout, float* __restrict__ impout)
{
    extern __shared__ char smem_raw[];
    Smem& sm = *reinterpret_cast<Smem*>(smem_raw);

    const int t  = threadIdx.x;
    const int b0 = blockIdx.x * MB;

    // ---- stage resident weights & init state ----
    for (int e = t; e < Hh * Dd; e += NT) sm.hist[e] = histW[e];
    for (int e = t; e < Dd * Dd; e += NT) {
        int k = e >> 6, jj = e & 63;
        sm.frT[e] = frW[jj * Dd + k];
    }
    if (t < Dd) { sm.hist_b[t] = histB[t]; sm.fr_b[t] = frB[t]; }
    for (int e = t; e < MB * Hh; e += NT) sm.cs[e] = 0.f;
    for (int e = t; e < Hh * 8; e += NT) sm.hq[e] = 0.f;
    {   // step-0 inputs + alpha[0]
        int r = t >> 6, jj = t & 63;
        int off = ((b0 + r) * Tt + 0) * Dd + jj;
        sm.xs[t] = values[off]; sm.ms[t] = masks[off];
        int j = t & 63, p = (t >> 6) & 3, par = t >> 8;
        sm.alp[p * 128 + j * 2 + par] = alpha_g[((b0 + 2 * p + par) * Tt + 0) * Dd + j];
    }
    __syncthreads();

    float pf_x[2], pf_m[2], pf_a0, pf_a1;   // wg1 prefetch regs

    for (int step = 0; step < Tt; ++step) {
        // ---- P1 (all): x_h partials, k-split 8-way, into zp alias ----
        float2* cpart = (float2*)sm.zp;
        {
            const int j = t & 63, kq = t >> 6;
            u64 a[4];
            #pragma unroll
            for (int p = 0; p < 4; p++) a[p] = 0ULL;
            const int k0 = kq * 32;
            #pragma unroll 4
            for (int kk = 0; kk < 32; kk++) {
                int k = k0 + kk;
                u64 wd = dup2(sm.hist[k * Dd + j]);
                float4 ha = *(const float4*)(sm.hq + k * 8);
                float4 hb = *(const float4*)(sm.hq + k * 8 + 4);
                a[0] = fma2(((const u64*)&ha)[0], wd, a[0]);
                a[1] = fma2(((const u64*)&ha)[1], wd, a[1]);
                a[2] = fma2(((const u64*)&hb)[0], wd, a[2]);
                a[3] = fma2(((const u64*)&hb)[1], wd, a[3]);
            }
            #pragma unroll
            for (int p = 0; p < 4; p++) {
                float a0, a1; upk2(a[p], a0, a1);
                cpart[(kq * 4 + p) * 64 + j] = make_float2(a0, a1);
            }
        }
        __syncthreads();

        // ---- P3: wg0 {reduce -> x_c; z_h -> c_c -> impout} | wg1 {prefetch} --
        if (t < 256) {
            const int j = t & 63, p = t >> 6;
            const float* cp = (const float*)cpart;
            float xh[2];
            #pragma unroll
            for (int par = 0; par < 2; par++) {
                float s = 0.f;
                #pragma unroll
                for (int kq = 0; kq < 8; kq++)
                    s += cp[((kq * 4 + p) * 64 + j) * 2 + par];
                xh[par] = s + sm.hist_b[j];
                int r = 2 * p + par;
                float m = sm.ms[r * Dd + j], x = sm.xs[r * Dd + j];
                float xc = m * x + (1.f - m) * xh[par];
                sm.xcp[p * 128 + j * 2 + par] = xc;
                sm.xhp[p * 128 + j * 2 + par] = xh[par];
            }
            asm volatile("bar.sync 1, 256;" ::: "memory");
            u64 z = dup2(sm.fr_b[j]);
            #pragma unroll 4
            for (int k = 0; k < Dd; k++)
                z = fma2(*(const u64*)(sm.xcp + p * 128 + k * 2),
                         dup2(sm.frT[k * Dd + j]), z);
            float z0, z1; upk2(z, z0, z1);
            float2 al = *(const float2*)(sm.alp + p * 128 + j * 2);
            int r0 = 2 * p, r1 = r0 + 1;
            float m0 = sm.ms[r0 * Dd + j], m1 = sm.ms[r1 * Dd + j];
            float x0 = sm.xs[r0 * Dd + j], x1 = sm.xs[r1 * Dd + j];
            float ch0 = al.x * z0 + (1.f - al.x) * xh[0];
            float ch1 = al.y * z1 + (1.f - al.y) * xh[1];
            float cc0 = m0 * x0 + (1.f - m0) * ch0;
            float cc1 = m1 * x1 + (1.f - m1) * ch1;
            *(float2*)(sm.ccq + j * 8 + 2 * p) = make_float2(cc0, cc1);
            impout[(r0 + b0) * Tt * Dd + step * Dd + j] = cc0;
            impout[(r1 + b0) * Tt * Dd + step * Dd + j] = cc1;
        } else if (step + 1 < Tt) {
            const int u = t - 256;
            #pragma unroll
            for (int s = 0; s < 2; s++) {
                int e = u + s * 256;
                int r = e >> 6, jj = e & 63;
                int off = ((b0 + r) * Tt + (step + 1)) * Dd + jj;
                pf_x[s] = values[off]; pf_m[s] = masks[off];
            }
            {
                int j = u & 63, rp = u >> 6;
                pf_a0 = alpha_g[((b0 + 2 * rp)     * Tt + step + 1) * Dd + j];
                pf_a1 = alpha_g[((b0 + 2 * rp + 1) * Tt + step + 1) * Dd + j];
            }
            {
                int r = u >> 5, c0 = (u & 31) * 8;
                const float* gsrc = Gh_g + ((b0 + r) * Tt + (step + 1)) * Hh + c0;
                float4 g0 = *(const float4*)gsrc;
                float4 g1 = *(const float4*)(gsrc + 4);
                *(float4*)(sm.gh + r * Hh + c0)     = g0;
                *(float4*)(sm.gh + r * Hh + c0 + 4) = g1;
            }
        }
        __syncthreads();

        // ---- P4 (all): z = zpre + h@Wrk + c_c@Wk ; (P=2 pairs, C=4 cols) ----
        {
            const int cg = t >> 1;     // column group: cols cg*4 .. cg*4+3
            const int pg = t & 1;      // pair group: pairs {2pg, 2pg+1}
            u64 acc[4][2];
            #pragma unroll
            for (int c = 0; c < 4; c++) { acc[c][0] = 0ULL; acc[c][1] = 0ULL; }

            // ---- recurrent part: K = 256 over lstmRK ----
            const float* __restrict__ Wr = lstmRK + cg * 4;
            float4 wbuf[4];
            #pragma unroll
            for (int i = 0; i < 4; i++) wbuf[i] = *(const float4*)(Wr + i * 1024);
            #pragma unroll 2
            for (int k = 0; k < Hh; k += 4) {
                float4 nbuf[4];
                int kn = (k + 4) & 255;
                #pragma unroll
                for (int i = 0; i < 4; i++)
                    nbuf[i] = *(const float4*)(Wr + (kn + i) * 1024);
                #pragma unroll
                for (int i = 0; i < 4; i++) {
                    float4 hv = *(const float4*)(sm.hq + (k + i) * 8 + pg * 4);
                    u64 hA = ((const u64*)&hv)[0], hB = ((const u64*)&hv)[1];
                    float4 w = wbuf[i];
                    u64 w0 = dup2(w.x), w1 = dup2(w.y), w2 = dup2(w.z), w3 = dup2(w.w);
                    acc[0][0] = fma2(hA, w0, acc[0][0]); acc[0][1] = fma2(hB, w0, acc[0][1]);
                    acc[1][0] = fma2(hA, w1, acc[1][0]); acc[1][1] = fma2(hB, w1, acc[1][1]);
                    acc[2][0] = fma2(hA, w2, acc[2][0]); acc[2][1] = fma2(hB, w2, acc[2][1]);
                    acc[3][0] = fma2(hA, w3, acc[3][0]); acc[3][1] = fma2(hB, w3, acc[3][1]);
                }
                #pragma unroll
                for (int i = 0; i < 4; i++) wbuf[i] = nbuf[i];
            }

            // ---- zpre loads issued here, consumed in epilogue ----
            u64 zin[2][4];
            #pragma unroll
            for (int pp = 0; pp < 2; pp++) {
                int p = 2 * pg + pp;
                const float* zb = zprep_g +
                    ((size_t)((b0 / 2 + p) * Tt + step) * 1024 + cg * 4) * 2;
                float4 v0 = *(const float4*)zb;
                float4 v1 = *(const float4*)(zb + 4);
                zin[pp][0] = ((const u64*)&v0)[0]; zin[pp][1] = ((const u64*)&v0)[1];
                zin[pp][2] = ((const u64*)&v1)[0]; zin[pp][3] = ((const u64*)&v1)[1];
            }

            // ---- c_c part: K = 64 over lstmK rows 0..63 ----
            const float* __restrict__ Wc = lstmK + cg * 4;
            #pragma unroll
            for (int i = 0; i < 4; i++) wbuf[i] = *(const float4*)(Wc + i * 1024);
            #pragma unroll 2
            for (int k = 0; k < Dd; k += 4) {
                float4 nbuf[4];
                int kn = (k + 4) & 63;
                #pragma unroll
                for (int i = 0; i < 4; i++)
                    nbuf[i] = *(const float4*)(Wc + (kn + i) * 1024);
                #pragma unroll
                for (int i = 0; i < 4; i++) {
                    float4 hv = *(const float4*)(sm.ccq + (k + i) * 8 + pg * 4);
                    u64 hA = ((const u64*)&hv)[0], hB = ((const u64*)&hv)[1];
                    float4 w = wbuf[i];
                    u64 w0 = dup2(w.x), w1 = dup2(w.y), w2 = dup2(w.z), w3 = dup2(w.w);
                    acc[0][0] = fma2(hA, w0, acc[0][0]); acc[0][1] = fma2(hB, w0, acc[0][1]);
                    acc[1][0] = fma2(hA, w1, acc[1][0]); acc[1][1] = fma2(hB, w1, acc[1][1]);
                    acc[2][0] = fma2(hA, w2, acc[2][0]); acc[2][1] = fma2(hB, w2, acc[2][1]);
                    acc[3][0] = fma2(hA, w3, acc[3][0]); acc[3][1] = fma2(hB, w3, acc[3][1]);
                }
                #pragma unroll
                for (int i = 0; i < 4; i++) wbuf[i] = nbuf[i];
            }

            // ---- epilogue: add zpre, activations, store to zp ----
            const int gate = cg >> 6;
            #pragma unroll
            for (int pp = 0; pp < 2; pp++) {
                float r[8];
                #pragma unroll
                for (int c = 0; c < 4; c++) {
                    u64 zv = add2(acc[c][pp], zin[pp][c]);
                    float v0, v1; upk2(zv, v0, v1);
                    if (gate == 2) { r[2 * c] = tanhfast(v0); r[2 * c + 1] = tanhfast(v1); }
                    else           { r[2 * c] = sigf(v0);     r[2 * c + 1] = sigf(v1);     }
                }
                int p = 2 * pg + pp;
                *(float4*)(sm.zp + p * 2048 + (cg * 4) * 2) =
                    make_float4(r[0], r[1], r[2], r[3]);
                *(float4*)(sm.zp + p * 2048 + (cg * 4 + 2) * 2) =
                    make_float4(r[4], r[5], r[6], r[7]);
            }
        }
        __syncthreads();

        // ---- P5: wg0 {c,h update + fused next-step decay} | wg1 {commit} ----
        if (t < 256) {
            int r = t >> 5;
            int p = r >> 1, par = r & 1;
            int cb = (t & 31) * 8;
            bool last = (step == Tt - 1);
            float4 gA = *(const float4*)(sm.gh + r * Hh + cb);
            float4 gB = *(const float4*)(sm.gh + r * Hh + cb + 4);
            float gv8[8] = {gA.x, gA.y, gA.z, gA.w, gB.x, gB.y, gB.z, gB.w};
            #pragma unroll
            for (int cc = 0; cc < 8; cc++) {
                int c = cb + cc;
                float iv = sm.zp[p * 2048 + (0 * Hh + c) * 2 + par];
                float fv = sm.zp[p * 2048 + (1 * Hh + c) * 2 + par];
                float gg = sm.zp[p * 2048 + (2 * Hh + c) * 2 + par];
                float ov = sm.zp[p * 2048 + (3 * Hh + c) * 2 + par];
                float cold = sm.cs[r * Hh + c];
                float cnew = fv * cold + iv * gg;
                sm.cs[r * Hh + c] = cnew;
                float hh = ov * tanhfast(cnew);
                if (!last) hh *= gv8[cc];
                sm.hq[c * 8 + r] = hh;
            }
        } else if (step + 1 < Tt) {
            const int u = t - 256;
            #pragma unroll
            for (int s = 0; s < 2; s++) {
                int e = u + s * 256;
                sm.xs[e] = pf_x[s]; sm.ms[e] = pf_m[s];
            }
            int j = u & 63, rp = u >> 6;
            *(float2*)(sm.alp + rp * 128 + j * 2) = make_float2(pf_a0, pf_a1);
        }
        __syncthreads();
    }

    // ---- final: y = h @ out_W + out_b ----
    {
        int w = t >> 5, lane = t & 31;
        if (w < MB) {
            float s = 0.f;
            for (int k = lane; k < Hh; k += 32)
                s += sm.hq[k * 8 + w] * outW[k];
            #pragma unroll
            for (int o = 16; o > 0; o >>= 1)
                s += __shfl_down_sync(0xffffffffu, s, o);
            if (lane == 0) yout[b0 + w] = s + outB[0];
        }
    }
}

// ================================ launcher ================================

extern "C" void kernel_launch(void* const* d_in, const int* in_sizes, int n_in,
                              void* d_out, int out_size) {
    const float* values = (const float*)d_in[0];
    const float* masks  = (const float*)d_in[1];
    const float* deltas = (const float*)d_in[2];
    const float* tdhW   = (const float*)d_in[3];
    const float* tdhB   = (const float*)d_in[4];
    const float* tdxW   = (const float*)d_in[5];
    const float* tdxB   = (const float*)d_in[6];
    const float* histW  = (const float*)d_in[7];
    const float* histB  = (const float*)d_in[8];
    const float* frW    = (const float*)d_in[9];
    const float* frB    = (const float*)d_in[10];
    const float* wcW    = (const float*)d_in[11];
    const float* wcB    = (const float*)d_in[12];
    const float* lstmK  = (const float*)d_in[13];
    const float* lstmRK = (const float*)d_in[14];
    const float* lstmB  = (const float*)d_in[15];
    const float* outW   = (const float*)d_in[16];
    const float* outB   = (const float*)d_in[17];

    float* yout   = (float*)d_out;       // y_h [B,1] first
    float* impout = yout + Bsz;          // imputations [B,T,D]

    transpose_kernel<<<(Hh * Dd + Dd * Dd + 255) / 256, 256>>>(tdhW, tdxW);

    int gasm = (64 * 256 + 64 * 64 + 128 * 64 + 3 * 512) * 4;   // ~118 KB
    cudaFuncSetAttribute(pre_ga_kernel, cudaFuncAttributeMaxDynamicSharedMemorySize, gasm);
    pre_ga_kernel<<<Bsz / 8, 256, gasm>>>(deltas, masks, tdhB, tdxB, wcW, wcB);

    int zsm = (64 * 256 + 256 + 16 * 128) * 4;   // ~73 KB
    cudaFuncSetAttribute(pre_z_kernel, cudaFuncAttributeMaxDynamicSharedMemorySize, zsm);
    pre_z_kernel<<<dim3(4, Bsz / 2), 256, zsm>>>(masks, lstmK, lstmB);

    cudaFuncSetAttribute(rits_kernel, cudaFuncAttributeMaxDynamicSharedMemorySize,
                         (int)sizeof(Smem));
    rits_kernel<<<GRID, NT, sizeof(Smem)>>>(
        values, masks, histW, histB, frW, frB,
        lstmK, lstmRK, outW, outB, yout, impout);
}

// round 8
// speedup vs baseline: 1.0480x; 1.0480x over previous
#include <cuda_runtime.h>
#include <cstdint>

#define Bsz 1024
#define Tt  128
#define Dd  64
#define Hh  256
#define MB  8
#define NT  512
#define GRID 128

typedef unsigned long long u64;

// ------------------- device scratch -------------------
__device__ float tdhT_g[Dd * Hh];                    // td_h_W^T  [k][c]
__device__ float tdxT_g[Dd * Dd];                    // td_x_W^T  [k][j]
__device__ float zprep_g[(Bsz / 2) * Tt * 1024 * 2]; // lstm_b + m@Wm, paired

__device__ __forceinline__ u64 dup2(float w) {
    u64 r; asm("mov.b64 %0, {%1,%1};" : "=l"(r) : "f"(w)); return r;
}
__device__ __forceinline__ void upk2(u64 v, float& lo, float& hi) {
    asm("mov.b64 {%0,%1}, %2;" : "=f"(lo), "=f"(hi) : "l"(v));
}
__device__ __forceinline__ u64 fma2(u64 a, u64 b, u64 c) {
    u64 d; asm("fma.rn.f32x2 %0, %1, %2, %3;" : "=l"(d) : "l"(a), "l"(b), "l"(c)); return d;
}
__device__ __forceinline__ u64 add2(u64 a, u64 b) {
    u64 d; asm("add.rn.f32x2 %0, %1, %2;" : "=l"(d) : "l"(a), "l"(b)); return d;
}
__device__ __forceinline__ float sigf(float x) {
    return __fdividef(1.f, 1.f + __expf(-x));
}
__device__ __forceinline__ float tanhfast(float x) {
    return __fdividef(2.f, 1.f + __expf(-2.f * x)) - 1.f;
}

// ============================ precompute kernels ============================

__global__ void transpose_kernel(const float* __restrict__ tdhW,
                                 const float* __restrict__ tdxW) {
    int idx = blockIdx.x * 256 + threadIdx.x;
    if (idx < Hh * Dd) {                       // tdhW (256,64) -> [k][c]
        int c = idx >> 6, k = idx & 63;
        tdhT_g[k * Hh + c] = tdhW[idx];
    } else if (idx < Hh * Dd + Dd * Dd) {      // tdxW (64,64) -> [k][j]
        int e = idx - Hh * Dd;
        int j = e >> 6, k = e & 63;
        tdxT_g[k * Dd + j] = tdxW[e];
    }
}

// zpre = lstm_b + m @ lstm_k[64:128], pair-interleaved (b even, b odd).
// grid (4 col-tiles, 512 b-pairs): W + bias staged ONCE, reused over all 128 t.
__global__ void __launch_bounds__(256) pre_z_kernel(
    const float* __restrict__ masks, const float* __restrict__ lstmK,
    const float* __restrict__ lstmB)
{
    extern __shared__ float psm[];
    float* W  = psm;               // [64][256]
    float* lb = W + 64 * 256;      // [256]
    float* mp = lb + 256;          // [16 t][64 k][2 par]
    const int tid = threadIdx.x;
    const int c0 = blockIdx.x * 256;
    const int bp = blockIdx.y;

    for (int e = tid; e < 64 * 256; e += 256) {
        int k = e >> 8, c = e & 255;
        W[e] = lstmK[(Dd + k) * 1024 + c0 + c];
    }
    lb[tid] = lstmB[c0 + tid];

    const int cq = tid & 63;
    const int pg = tid >> 6;

    for (int t0 = 0; t0 < Tt; t0 += 16) {
        __syncthreads();
        #pragma unroll
        for (int par = 0; par < 2; par++)
            for (int e = tid; e < 16 * 64; e += 256) {
                int tt = e >> 6, k = e & 63;
                mp[tt * 128 + k * 2 + par] =
                    masks[((2 * bp + par) * Tt + t0 + tt) * Dd + k];
            }
        __syncthreads();

        u64 acc[4][4];
        #pragma unroll
        for (int tt = 0; tt < 4; tt++)
            #pragma unroll
            for (int c = 0; c < 4; c++) acc[tt][c] = 0ULL;

        #pragma unroll 2
        for (int k = 0; k < Dd; k++) {
            float4 w = *(const float4*)(W + k * 256 + cq * 4);
            u64 w0 = dup2(w.x), w1 = dup2(w.y), w2 = dup2(w.z), w3 = dup2(w.w);
            #pragma unroll
            for (int tt = 0; tt < 4; tt++) {
                u64 m2 = *(const u64*)(mp + (pg * 4 + tt) * 128 + k * 2);
                acc[tt][0] = fma2(m2, w0, acc[tt][0]);
                acc[tt][1] = fma2(m2, w1, acc[tt][1]);
                acc[tt][2] = fma2(m2, w2, acc[tt][2]);
                acc[tt][3] = fma2(m2, w3, acc[tt][3]);
            }
        }
        float4 lbv = *(const float4*)(lb + cq * 4);
        u64 lb0 = dup2(lbv.x), lb1 = dup2(lbv.y), lb2 = dup2(lbv.z), lb3 = dup2(lbv.w);
        #pragma unroll
        for (int tt = 0; tt < 4; tt++) {
            int tg = t0 + pg * 4 + tt;
            int col = c0 + cq * 4;
            u64* dst = (u64*)(zprep_g + ((size_t)(bp * Tt + tg) * 1024 + col) * 2);
            dst[0] = add2(acc[tt][0], lb0);
            dst[1] = add2(acc[tt][1], lb1);
            dst[2] = add2(acc[tt][2], lb2);
            dst[3] = add2(acc[tt][3], lb3);
        }
    }
}

// ============================ main recurrent kernel ============================

struct __align__(16) Smem {
    float hist[Hh * Dd];      // 64 KB
    float frT[Dd * Dd];       // 16 KB
    float wcs[2 * Dd * Dd];   // 32 KB  wc_W [k][j]
    float tdxs[Dd * Dd];      // 16 KB  td_x_W^T [k][j]
    float hp[4 * 2 * Hh];     //  8 KB  h paired [p][c*2+par]
    float cs[MB * Hh];        //  8 KB
    float zp[4 * 2 * 4 * Hh]; // 32 KB  gate acts (alias: x_h partials)
    float gh[4 * 2 * Hh];     //  8 KB  gamma_h(step+1), hp-paired layout
    float xs[MB * Dd], ms[MB * Dd];
    float dp[4 * 2 * Dd], mp[4 * 2 * Dd];
    float gxp[4 * 2 * Dd], alp[4 * 2 * Dd];
    float xcp[4 * 2 * Dd], xhp[4 * 2 * Dd], ccp[4 * 2 * Dd];
    float hist_b[Dd], fr_b[Dd];
};

template <int STRIDE>
__device__ __forceinline__ void eblk(const float* src, int k0,
                                     float2 w0, float2 w1, u64 (&acc)[4][2]) {
    u64 wa0 = dup2(w0.x), wb0 = dup2(w0.y);
    u64 wa1 = dup2(w1.x), wb1 = dup2(w1.y);
    #pragma unroll
    for (int p = 0; p < 4; p++) {
        float4 hv = *(const float4*)(src + p * STRIDE + k0 * 2);
        u64 h0 = ((const u64*)&hv)[0];
        u64 h1 = ((const u64*)&hv)[1];
        acc[p][0] = fma2(h0, wa0, acc[p][0]);
        acc[p][1] = fma2(h0, wb0, acc[p][1]);
        acc[p][0] = fma2(h1, wa1, acc[p][0]);
        acc[p][1] = fma2(h1, wb1, acc[p][1]);
    }
}

__global__ void __launch_bounds__(NT, 1) rits_kernel(
    const float* __restrict__ values, const float* __restrict__ masks,
    const float* __restrict__ deltas,
    const float* __restrict__ tdhB, const float* __restrict__ tdxB,
    const float* __restrict__ histW, const float* __restrict__ histB,
    const float* __restrict__ frW, const float* __restrict__ frB,
    const float* __restrict__ wcW, const float* __restrict__ wcB,
    const float* __restrict__ lstmK, const float* __restrict__ lstmRK,
    const float* __restrict__ outW, const float* __restrict__ outB,
    float* __restrict__ yout, float* __restrict__ impout)
{
    extern __shared__ char smem_raw[];
    Smem& sm = *reinterpret_cast<Smem*>(smem_raw);

    const int t  = threadIdx.x;
    const int b0 = blockIdx.x * MB;

    // ---- stage resident weights & init state ----
    for (int e = t; e < Hh * Dd; e += NT) sm.hist[e] = histW[e];
    for (int e = t; e < Dd * Dd; e += NT) {
        int k = e >> 6, jj = e & 63;
        sm.frT[e]  = frW[jj * Dd + k];
        sm.tdxs[e] = tdxT_g[e];
    }
    for (int e = t; e < 2 * Dd * Dd; e += NT) sm.wcs[e] = wcW[e];
    if (t < Dd) { sm.hist_b[t] = histB[t]; sm.fr_b[t] = frB[t]; }
    for (int e = t; e < MB * Hh; e += NT) sm.cs[e] = 0.f;
    for (int e = t; e < 4 * 2 * Hh; e += NT) sm.hp[e] = 0.f;

    // per-thread bias registers for wg1's gamma/alpha work
    float bh = 0.f, bx = 0.f, bw = 0.f;
    if (t >= 256) {
        int u = t - 256;
        bh = tdhB[u]; bx = tdxB[u & 63]; bw = wcB[u & 63];
    }

    {   // step-0 inputs
        int r = t >> 6, jj = t & 63;
        int off = ((b0 + r) * Tt + 0) * Dd + jj;
        float xv = values[off], mv = masks[off], dv = deltas[off];
        sm.xs[t] = xv; sm.ms[t] = mv;
        int pr = (r >> 1) * 128 + jj * 2 + (r & 1);
        sm.mp[pr] = mv; sm.dp[pr] = dv;
    }
    __syncthreads();

    // ---- prologue: alpha(0) (gamma_x -> alpha) by wg1 ----
    if (t >= 256) {
        const int u = t - 256;
        const int j = u & 63, pg = u >> 6;
        u64 g = dup2(bx);
        #pragma unroll 4
        for (int k = 0; k < Dd; k++)
            g = fma2(*(const u64*)(sm.dp + pg * 128 + k * 2),
                     dup2(sm.tdxs[k * Dd + j]), g);
        float g0, g1; upk2(g, g0, g1);
        sm.gxp[pg * 128 + j * 2 + 0] = __expf(-fmaxf(g0, 0.f));
        sm.gxp[pg * 128 + j * 2 + 1] = __expf(-fmaxf(g1, 0.f));
    }
    __syncthreads();
    if (t >= 256) {
        const int u = t - 256;
        const int j = u & 63, pg = u >> 6;
        u64 al = dup2(bw);
        #pragma unroll 4
        for (int k = 0; k < Dd; k++) {
            al = fma2(*(const u64*)(sm.gxp + pg * 128 + k * 2), dup2(sm.wcs[k * Dd + j]), al);
            al = fma2(*(const u64*)(sm.mp  + pg * 128 + k * 2), dup2(sm.wcs[(Dd + k) * Dd + j]), al);
        }
        float a0, a1; upk2(al, a0, a1);
        *(float2*)(sm.alp + pg * 128 + j * 2) = make_float2(a0, a1);
    }
    __syncthreads();

    float pf_x[2], pf_m[2], pf_d[2];   // wg1 prefetch regs

    for (int step = 0; step < Tt; ++step) {
        // ---- P0: apply gamma_h decay to h (computed last step by wg1) ----
        if (step && t < 256) {
            float4* H = (float4*)sm.hp;
            float4* G = (float4*)sm.gh;
            #pragma unroll
            for (int s = 0; s < 2; s++) {
                int i = t + s * 256;
                float4 h = H[i], g = G[i];
                h.x *= g.x; h.y *= g.y; h.z *= g.z; h.w *= g.w;
                H[i] = h;
            }
        }
        __syncthreads();

        // ---- P1 (all): x_h partials, k-split 8-way, into zp alias ----
        float2* cpart = (float2*)sm.zp;
        {
            const int j = t & 63, kq = t >> 6;
            u64 a[4];
            #pragma unroll
            for (int p = 0; p < 4; p++) a[p] = 0ULL;
            const int k0 = kq * 32;
            #pragma unroll 4
            for (int kk = 0; kk < 32; kk++) {
                int k = k0 + kk;
                u64 wd = dup2(sm.hist[k * Dd + j]);
                #pragma unroll
                for (int p = 0; p < 4; p++)
                    a[p] = fma2(*(const u64*)(sm.hp + p * 512 + k * 2), wd, a[p]);
            }
            #pragma unroll
            for (int p = 0; p < 4; p++) {
                float a0, a1; upk2(a[p], a0, a1);
                cpart[(kq * 4 + p) * 64 + j] = make_float2(a0, a1);
            }
        }
        __syncthreads();

        // ---- P3: wg0 {reduce -> x_c; z_h -> c_c -> impout} | wg1 {prefetch} --
        if (t < 256) {
            const int j = t & 63, p = t >> 6;
            const float* cp = (const float*)cpart;
            float xh[2];
            #pragma unroll
            for (int par = 0; par < 2; par++) {
                float s = 0.f;
                #pragma unroll
                for (int kq = 0; kq < 8; kq++)
                    s += cp[((kq * 4 + p) * 64 + j) * 2 + par];
                xh[par] = s + sm.hist_b[j];
                int r = 2 * p + par;
                float m = sm.ms[r * Dd + j], x = sm.xs[r * Dd + j];
                float xc = m * x + (1.f - m) * xh[par];
                sm.xcp[p * 128 + j * 2 + par] = xc;
                sm.xhp[p * 128 + j * 2 + par] = xh[par];
            }
            asm volatile("bar.sync 1, 256;" ::: "memory");
            u64 z = dup2(sm.fr_b[j]);
            #pragma unroll 4
            for (int k = 0; k < Dd; k++)
                z = fma2(*(const u64*)(sm.xcp + p * 128 + k * 2),
                         dup2(sm.frT[k * Dd + j]), z);
            float z0, z1; upk2(z, z0, z1);
            float2 al = *(const float2*)(sm.alp + p * 128 + j * 2);
            int r0 = 2 * p, r1 = r0 + 1;
            float m0 = sm.ms[r0 * Dd + j], m1 = sm.ms[r1 * Dd + j];
            float x0 = sm.xs[r0 * Dd + j], x1 = sm.xs[r1 * Dd + j];
            float ch0 = al.x * z0 + (1.f - al.x) * xh[0];
            float ch1 = al.y * z1 + (1.f - al.y) * xh[1];
            float cc0 = m0 * x0 + (1.f - m0) * ch0;
            float cc1 = m1 * x1 + (1.f - m1) * ch1;
            *(float2*)(sm.ccp + p * 128 + j * 2) = make_float2(cc0, cc1);
            impout[(r0 + b0) * Tt * Dd + step * Dd + j] = cc0;
            impout[(r1 + b0) * Tt * Dd + step * Dd + j] = cc1;
        } else if (step + 1 < Tt) {
            const int u = t - 256;
            #pragma unroll
            for (int s = 0; s < 2; s++) {
                int e = u + s * 256;
                int r = e >> 6, jj = e & 63;
                int off = ((b0 + r) * Tt + (step + 1)) * Dd + jj;
                pf_x[s] = values[off]; pf_m[s] = masks[off]; pf_d[s] = deltas[off];
            }
        }
        __syncthreads();

        // ---- P4 (all): z = zpre + h@Wrk + c_c@Wk ; distance-8 pipeline ----
        {
            u64 acc[4][2];
            #pragma unroll
            for (int p = 0; p < 4; p++) { acc[p][0] = 0ULL; acc[p][1] = 0ULL; }

            const float2* rk2 = (const float2*)lstmRK;
            float2 a0 = rk2[t],        a1 = rk2[512 + t];
            float2 a2 = rk2[1024 + t], a3 = rk2[1536 + t];
            float2 c0 = rk2[2048 + t], c1 = rk2[2560 + t];
            float2 c2 = rk2[3072 + t], c3 = rk2[3584 + t];
            #pragma unroll 2
            for (int k = 0; k < Hh; k += 8) {
                int kn = (k + 8) & 255;
                float2 na0 = rk2[kn * 512 + t],       na1 = rk2[(kn + 1) * 512 + t];
                float2 na2 = rk2[(kn + 2) * 512 + t], na3 = rk2[(kn + 3) * 512 + t];
                eblk<512>(sm.hp, k,     a0, a1, acc);
                eblk<512>(sm.hp, k + 2, a2, a3, acc);
                int km = (k + 12) & 255;
                float2 nc0 = rk2[km * 512 + t],       nc1 = rk2[(km + 1) * 512 + t];
                float2 nc2 = rk2[(km + 2) * 512 + t], nc3 = rk2[(km + 3) * 512 + t];
                eblk<512>(sm.hp, k + 4, c0, c1, acc);
                eblk<512>(sm.hp, k + 6, c2, c3, acc);
                a0 = na0; a1 = na1; a2 = na2; a3 = na3;
                c0 = nc0; c1 = nc1; c2 = nc2; c3 = nc3;
            }

            u64 zin[4][2];
            const float4* zp4 = (const float4*)zprep_g;
            #pragma unroll
            for (int p = 0; p < 4; p++) {
                float4 v = zp4[((size_t)(b0 / 2 + p) * Tt + step) * 512 + t];
                zin[p][0] = ((const u64*)&v)[0];
                zin[p][1] = ((const u64*)&v)[1];
            }

            const float2* kk2 = (const float2*)lstmK;
            a0 = kk2[t];        a1 = kk2[512 + t];
            a2 = kk2[1024 + t]; a3 = kk2[1536 + t];
            c0 = kk2[2048 + t]; c1 = kk2[2560 + t];
            c2 = kk2[3072 + t]; c3 = kk2[3584 + t];
            #pragma unroll 2
            for (int k = 0; k < Dd; k += 8) {
                int kn = (k + 8) & 63;
                float2 na0 = kk2[kn * 512 + t],       na1 = kk2[(kn + 1) * 512 + t];
                float2 na2 = kk2[(kn + 2) * 512 + t], na3 = kk2[(kn + 3) * 512 + t];
                eblk<128>(sm.ccp, k,     a0, a1, acc);
                eblk<128>(sm.ccp, k + 2, a2, a3, acc);
                int km = (k + 12) & 63;
                float2 nc0 = kk2[km * 512 + t],       nc1 = kk2[(km + 1) * 512 + t];
                float2 nc2 = kk2[(km + 2) * 512 + t], nc3 = kk2[(km + 3) * 512 + t];
                eblk<128>(sm.ccp, k + 4, c0, c1, acc);
                eblk<128>(sm.ccp, k + 6, c2, c3, acc);
                a0 = na0; a1 = na1; a2 = na2; a3 = na3;
                c0 = nc0; c1 = nc1; c2 = nc2; c3 = nc3;
            }

            const int gate = t >> 7;
            #pragma unroll
            for (int p = 0; p < 4; p++) {
                #pragma unroll
                for (int q = 0; q < 2; q++) {
                    u64 zv = add2(acc[p][q], zin[p][q]);
                    float v0, v1; upk2(zv, v0, v1);
                    float b0f, b1f;
                    if (gate == 2) { b0f = tanhfast(v0); b1f = tanhfast(v1); }
                    else           { b0f = sigf(v0);     b1f = sigf(v1);     }
                    int col = 2 * t + q;
                    *(float2*)(sm.zp + p * 2048 + col * 2) = make_float2(b0f, b1f);
                }
            }
        }
        __syncthreads();

        // ---- P5: wg0 {c,h update} | wg1 {commit inputs; gamma_h/gamma_x/alpha} --
        if (t < 256) {
            int r = t >> 5;
            int p = r >> 1, par = r & 1;
            int cb = (t & 31) * 8;
            #pragma unroll
            for (int cc = 0; cc < 8; cc++) {
                int c = cb + cc;
                float iv = sm.zp[p * 2048 + (0 * Hh + c) * 2 + par];
                float fv = sm.zp[p * 2048 + (1 * Hh + c) * 2 + par];
                float gg = sm.zp[p * 2048 + (2 * Hh + c) * 2 + par];
                float ov = sm.zp[p * 2048 + (3 * Hh + c) * 2 + par];
                float cold = sm.cs[r * Hh + c];
                float cnew = fv * cold + iv * gg;
                sm.cs[r * Hh + c] = cnew;
                sm.hp[p * 512 + c * 2 + par] = ov * tanhfast(cnew);
            }
        } else if (step + 1 < Tt) {
            const int u = t - 256;
            // commit prefetched step+1 inputs
            #pragma unroll
            for (int s = 0; s < 2; s++) {
                int e = u + s * 256;
                int r = e >> 6, jj = e & 63;
                sm.xs[e] = pf_x[s]; sm.ms[e] = pf_m[s];
                int pr = (r >> 1) * 128 + jj * 2 + (r & 1);
                sm.mp[pr] = pf_m[s]; sm.dp[pr] = pf_d[s];
            }
            asm volatile("bar.sync 2, 256;" ::: "memory");
            // gamma_h(step+1): thread = column c, 4 pair accumulators
            {
                const int c = u;
                u64 a[4];
                #pragma unroll
                for (int p = 0; p < 4; p++) a[p] = 0ULL;
                #pragma unroll 4
                for (int k = 0; k < Dd; k++) {
                    u64 wd = dup2(tdhT_g[k * Hh + c]);
                    #pragma unroll
                    for (int p = 0; p < 4; p++)
                        a[p] = fma2(*(const u64*)(sm.dp + p * 128 + k * 2), wd, a[p]);
                }
                #pragma unroll
                for (int p = 0; p < 4; p++) {
                    float a0, a1; upk2(a[p], a0, a1);
                    float g0 = __expf(-fmaxf(a0 + bh, 0.f));
                    float g1 = __expf(-fmaxf(a1 + bh, 0.f));
                    *(float2*)(sm.gh + p * 512 + c * 2) = make_float2(g0, g1);
                }
            }
            // gamma_x(step+1)
            const int j = u & 63, pg = u >> 6;
            {
                u64 g = dup2(bx);
                #pragma unroll 4
                for (int k = 0; k < Dd; k++)
                    g = fma2(*(const u64*)(sm.dp + pg * 128 + k * 2),
                             dup2(sm.tdxs[k * Dd + j]), g);
                float g0, g1; upk2(g, g0, g1);
                sm.gxp[pg * 128 + j * 2 + 0] = __expf(-fmaxf(g0, 0.f));
                sm.gxp[pg * 128 + j * 2 + 1] = __expf(-fmaxf(g1, 0.f));
            }
            asm volatile("bar.sync 2, 256;" ::: "memory");
            // alpha(step+1)
            {
                u64 al = dup2(bw);
                #pragma unroll 4
                for (int k = 0; k < Dd; k++) {
                    al = fma2(*(const u64*)(sm.gxp + pg * 128 + k * 2),
                              dup2(sm.wcs[k * Dd + j]), al);
                    al = fma2(*(const u64*)(sm.mp + pg * 128 + k * 2),
                              dup2(sm.wcs[(Dd + k) * Dd + j]), al);
                }
                float a0, a1; upk2(al, a0, a1);
                *(float2*)(sm.alp + pg * 128 + j * 2) = make_float2(a0, a1);
            }
        }
        __syncthreads();
    }

    // ---- final: y = h @ out_W + out_b ----
    {
        int w = t >> 5, lane = t & 31;
        if (w < MB) {
            float s = 0.f;
            for (int k = lane; k < Hh; k += 32)
                s += sm.hp[(w >> 1) * 512 + k * 2 + (w & 1)] * outW[k];
            #pragma unroll
            for (int o = 16; o > 0; o >>= 1)
                s += __shfl_down_sync(0xffffffffu, s, o);
            if (lane == 0) yout[b0 + w] = s + outB[0];
        }
    }
}

// ================================ launcher ================================

extern "C" void kernel_launch(void* const* d_in, const int* in_sizes, int n_in,
                              void* d_out, int out_size) {
    const float* values = (const float*)d_in[0];
    const float* masks  = (const float*)d_in[1];
    const float* deltas = (const float*)d_in[2];
    const float* tdhW   = (const float*)d_in[3];
    const float* tdhB   = (const float*)d_in[4];
    const float* tdxW   = (const float*)d_in[5];
    const float* tdxB   = (const float*)d_in[6];
    const float* histW  = (const float*)d_in[7];
    const float* histB  = (const float*)d_in[8];
    const float* frW    = (const float*)d_in[9];
    const float* frB    = (const float*)d_in[10];
    const float* wcW    = (const float*)d_in[11];
    const float* wcB    = (const float*)d_in[12];
    const float* lstmK  = (const float*)d_in[13];
    const float* lstmRK = (const float*)d_in[14];
    const float* lstmB  = (const float*)d_in[15];
    const float* outW   = (const float*)d_in[16];
    const float* outB   = (const float*)d_in[17];

    float* yout   = (float*)d_out;       // y_h [B,1] first
    float* impout = yout + Bsz;          // imputations [B,T,D]

    transpose_kernel<<<(Hh * Dd + Dd * Dd + 255) / 256, 256>>>(tdhW, tdxW);

    int zsm = (64 * 256 + 256 + 16 * 128) * 4;   // ~73 KB
    cudaFuncSetAttribute(pre_z_kernel, cudaFuncAttributeMaxDynamicSharedMemorySize, zsm);
    pre_z_kernel<<<dim3(4, Bsz / 2), 256, zsm>>>(masks, lstmK, lstmB);

    cudaFuncSetAttribute(rits_kernel, cudaFuncAttributeMaxDynamicSharedMemorySize,
                         (int)sizeof(Smem));
    rits_kernel<<<GRID, NT, sizeof(Smem)>>>(
        values, masks, deltas, tdhB, tdxB, histW, histB, frW, frB,
        wcW, wcB, lstmK, lstmRK, outW, outB, yout, impout);
}